// round 1
// baseline (speedup 1.0000x reference)
#include <cuda_runtime.h>
#include <math.h>

#define NN 3072
#define DD 3
#define MM 128
#define NB 128
#define NBLK (NN/NB)   // 24
#define JITTER_F 1e-8f

// ---------------- scratch (device globals; no allocations allowed) ----------
__device__ float g_K[NN*NN];            // kernel matrix / Cholesky factor (in-place)
__device__ float g_l[NN*DD];            // local lengthscales per point/dim
__device__ float g_alpha[DD*MM];        // local GP alphas
__device__ float g_yc[NN];              // centered y
__device__ float g_x[NN];               // solve vector (yc -> z -> alpha)
__device__ volatile int g_flagF[NBLK];
__device__ volatile int g_flagB[NBLK];

// ---------------- prep: mean-center y, reset flags --------------------------
__global__ void prep_kernel(const float* __restrict__ y) {
    __shared__ double red[1024];
    int t = threadIdx.x;
    double s = 0.0;
    for (int i = t; i < NN; i += 1024) s += (double)y[i];
    red[t] = s; __syncthreads();
    for (int o = 512; o > 0; o >>= 1) { if (t < o) red[t] += red[t+o]; __syncthreads(); }
    float mean = (float)(red[0] / (double)NN);
    for (int i = t; i < NN; i += 1024) {
        float v = y[i] - mean;
        g_yc[i] = v;
        g_x[i]  = v;
    }
    if (t < NBLK) { g_flagF[t] = 0; g_flagB[t] = 0; }
}

// ---------------- local GP: 128x128 chol + solve per dim (3 blocks) ---------
__global__ void local_chol_kernel(const float* __restrict__ X_bar,
                                  const float* __restrict__ lls,
                                  const float* __restrict__ lstd,
                                  const float* __restrict__ lnoise,
                                  const float* __restrict__ local_ls) {
    extern __shared__ float sh[];
    float* Ls = sh;                 // [128][129]
    float* xs = sh + 128*129;       // [128]
    float* xb = xs + 128;           // [128]
    int d = blockIdx.x;
    int t = threadIdx.x;
    float ls = lls[d], sd = lstd[d], no = lnoise[d];
    float inv2 = 0.5f / (ls*ls);
    float s2 = sd*sd;
    xb[t] = X_bar[t*DD + d];
    __syncthreads();
    float xt = xb[t];
    for (int j = 0; j < MM; ++j) {
        float diff = xt - xb[j];
        float dist = diff*diff;
        if (dist == 0.0f) dist = 1e-20f;
        float v = s2 * expf(-dist * inv2);
        if (j == t) v += no*no;
        Ls[t*129 + j] = v;
    }
    __syncthreads();
    // in-smem Cholesky (lower)
    for (int j = 0; j < MM; ++j) {
        if (t == 0) Ls[j*129 + j] = sqrtf(Ls[j*129 + j]);
        __syncthreads();
        float dj = Ls[j*129 + j];
        if (t > j) Ls[t*129 + j] /= dj;
        __syncthreads();
        if (t > j) {
            float ltj = Ls[t*129 + j];
            for (int c = j+1; c <= t; ++c) Ls[t*129 + c] -= ltj * Ls[c*129 + j];
        }
        __syncthreads();
    }
    // rhs = log|local_ls[:,d]|
    xs[t] = logf(fabsf(local_ls[t*DD + d]));
    __syncthreads();
    // forward L z = rhs
    for (int j = 0; j < MM; ++j) {
        if (t == j) xs[j] /= Ls[j*129 + j];
        __syncthreads();
        if (t > j) xs[t] -= Ls[t*129 + j] * xs[j];
        __syncthreads();
    }
    // backward L^T a = z
    for (int j = MM-1; j >= 0; --j) {
        if (t == j) xs[j] /= Ls[j*129 + j];
        __syncthreads();
        if (t < j) xs[t] -= Ls[j*129 + t] * xs[j];
        __syncthreads();
    }
    g_alpha[d*MM + t] = xs[t];
}

// ---------------- l = exp(k_star @ alpha) ------------------------------------
__global__ void compute_l_kernel(const float* __restrict__ X,
                                 const float* __restrict__ X_bar,
                                 const float* __restrict__ lls,
                                 const float* __restrict__ lstd) {
    __shared__ float xb[DD][MM];
    __shared__ float al[DD][MM];
    int t = threadIdx.x;
    for (int d = 0; d < DD; ++d) {
        xb[d][t] = X_bar[t*DD + d];
        al[d][t] = g_alpha[d*MM + t];
    }
    __syncthreads();
    int i = blockIdx.x * 128 + t;
    for (int d = 0; d < DD; ++d) {
        float ls = lls[d], sd = lstd[d];
        float inv2 = 0.5f / (ls*ls);
        float s2 = sd*sd;
        float xi = X[i*DD + d];
        float acc = 0.0f;
        #pragma unroll 4
        for (int j = 0; j < MM; ++j) {
            float diff = xi - xb[d][j];
            acc += s2 * expf(-diff*diff*inv2) * al[d][j];
        }
        g_l[i*DD + d] = expf(acc);
    }
}

// ---------------- build global K matrix --------------------------------------
__global__ void buildK_kernel(const float* __restrict__ X,
                              const float* __restrict__ gstd,
                              const float* __restrict__ gnoise) {
    __shared__ float xj[32][DD], lj[32][DD], xi[8][DD], li[8][DD];
    int tx = threadIdx.x, ty = threadIdx.y;
    int lt = ty*32 + tx;
    int jb = blockIdx.x*32, ib = blockIdx.y*8;
    if (lt < 32*DD) { int c = lt/DD, d = lt%DD; xj[c][d] = X[(jb+c)*DD+d]; lj[c][d] = g_l[(jb+c)*DD+d]; }
    else if (lt < 32*DD + 8*DD) { int q = lt - 32*DD; int r = q/DD, d = q%DD;
        xi[r][d] = X[(ib+r)*DD+d]; li[r][d] = g_l[(ib+r)*DD+d]; }
    __syncthreads();
    int j = jb + tx, i = ib + ty;
    float g2 = gstd[0]*gstd[0];
    float prod = 1.0f, sdist = 0.0f;
    #pragma unroll
    for (int d = 0; d < DD; ++d) {
        float a = li[ty][d], b = lj[tx][d];
        float den = a*a + b*b;
        prod *= 2.0f*a*b/den;
        float diff = xi[ty][d] - xj[tx][d];
        sdist += diff*diff/den;
    }
    float v = g2 * sqrtf(prod) * expf(-sdist);
    if (i == j) v += gnoise[0]*gnoise[0] + JITTER_F;
    g_K[i*NN + j] = v;
}

// ---------------- blocked Cholesky: diag factor ------------------------------
__global__ void potrf_kernel(int k) {
    extern __shared__ float sh[];
    float* Ls = sh;   // [128][129]
    int t = threadIdx.x;
    int base = k*NB;
    for (int idx = t; idx < NB*NB; idx += NB) {
        int r = idx >> 7, c = idx & 127;
        Ls[r*129 + c] = g_K[(base+r)*NN + base + c];
    }
    __syncthreads();
    for (int j = 0; j < NB; ++j) {
        if (t == 0) Ls[j*129 + j] = sqrtf(Ls[j*129 + j]);
        __syncthreads();
        float dj = Ls[j*129 + j];
        if (t > j) Ls[t*129 + j] /= dj;
        __syncthreads();
        if (t > j) {
            float ltj = Ls[t*129 + j];
            #pragma unroll 4
            for (int c = j+1; c <= t; ++c) Ls[t*129 + c] -= ltj * Ls[c*129 + j];
        }
        __syncthreads();
    }
    for (int idx = t; idx < NB*NB; idx += NB) {
        int r = idx >> 7, c = idx & 127;
        g_K[(base+r)*NN + base + c] = Ls[r*129 + c];
    }
}

// ---------------- blocked Cholesky: panel trsm (L21 = A21 * L11^-T) ----------
__global__ void trsm_kernel(int k) {
    extern __shared__ float sh[];
    float* Ls = sh;            // [128][128] (broadcast reads, no pad needed)
    float* Xs = sh + NB*NB;    // [128][129]
    int t = threadIdx.x;
    int rb = (k + 1 + blockIdx.x) * NB;
    int cb = k * NB;
    for (int idx = t; idx < NB*NB; idx += NB) {
        int r = idx >> 7, c = idx & 127;
        Ls[idx] = g_K[(cb+r)*NN + cb + c];
        Xs[r*129 + c] = g_K[(rb+r)*NN + cb + c];
    }
    __syncthreads();
    float* xr = Xs + t*129;
    for (int j = 0; j < NB; ++j) {
        float s = xr[j];
        #pragma unroll 4
        for (int kk = 0; kk < j; ++kk) s -= xr[kk] * Ls[j*128 + kk];
        xr[j] = s / Ls[j*128 + j];
    }
    __syncthreads();
    for (int idx = t; idx < NB*NB; idx += NB) {
        int r = idx >> 7, c = idx & 127;
        g_K[(rb+r)*NN + cb + c] = Xs[r*129 + c];
    }
}

// ---------------- blocked Cholesky: trailing syrk A22 -= L21 L21^T -----------
__global__ void syrk_kernel(int k) {
    int off = (k + 1) * NB;
    int bi = blockIdx.y, bj = blockIdx.x;
    if (bj > bi) return;   // lower tiles only
    __shared__ float As[64][17], Bs[64][17];
    int lt = threadIdx.x;
    int tx = lt & 15, ty = lt >> 4;
    int row0 = off + bi*64, col0 = off + bj*64;
    int pb = k * NB;
    float acc[4][4] = {};
    for (int p0 = 0; p0 < NB; p0 += 16) {
        #pragma unroll
        for (int q = 0; q < 4; ++q) {
            int e = lt + q*256;
            int r = e >> 4, c = e & 15;
            As[r][c] = g_K[(row0+r)*NN + pb + p0 + c];
            Bs[r][c] = g_K[(col0+r)*NN + pb + p0 + c];
        }
        __syncthreads();
        #pragma unroll
        for (int p = 0; p < 16; ++p) {
            float ar[4], br[4];
            #pragma unroll
            for (int a = 0; a < 4; ++a) ar[a] = As[ty + 16*a][p];
            #pragma unroll
            for (int b = 0; b < 4; ++b) br[b] = Bs[tx + 16*b][p];
            #pragma unroll
            for (int a = 0; a < 4; ++a)
                #pragma unroll
                for (int b = 0; b < 4; ++b) acc[a][b] += ar[a]*br[b];
        }
        __syncthreads();
    }
    #pragma unroll
    for (int a = 0; a < 4; ++a) {
        int r = row0 + ty + 16*a;
        #pragma unroll
        for (int b = 0; b < 4; ++b) {
            int c = col0 + tx + 16*b;
            g_K[r*NN + c] -= acc[a][b];
        }
    }
}

// ---------------- pipelined blocked forward solve L z = yc -------------------
__global__ void fwd_solve_kernel() {
    extern __shared__ float sh[];
    float* Ls = sh;                  // [128][129] diag block
    float* Lb = sh + 128*129;        // [128][129] off-diag block
    float* xs = Lb + 128*129;        // [128]
    float* xc = xs + 128;            // [128]
    int b = blockIdx.x, t = threadIdx.x;
    for (int idx = t; idx < NB*NB; idx += NB) {
        int r = idx >> 7, c = idx & 127;
        Ls[r*129 + c] = g_K[(b*NB+r)*NN + b*NB + c];
    }
    xs[t] = g_x[b*NB + t];
    __syncthreads();
    for (int c = 0; c < b; ++c) {
        if (t == 0) { while (g_flagF[c] == 0) __nanosleep(20); }
        __syncthreads();
        __threadfence();
        for (int idx = t; idx < NB*NB; idx += NB) {
            int r = idx >> 7, cc = idx & 127;
            Lb[r*129 + cc] = g_K[(b*NB+r)*NN + c*NB + cc];
        }
        xc[t] = g_x[c*NB + t];
        __syncthreads();
        float s = 0.0f;
        float* lr = Lb + t*129;
        #pragma unroll 8
        for (int j = 0; j < NB; ++j) s += lr[j] * xc[j];
        xs[t] -= s;
        __syncthreads();
    }
    for (int j = 0; j < NB; ++j) {
        if (t == j) xs[j] /= Ls[j*129 + j];
        __syncthreads();
        if (t > j) xs[t] -= Ls[t*129 + j] * xs[j];
        __syncthreads();
    }
    g_x[b*NB + t] = xs[t];
    __threadfence();
    __syncthreads();
    if (t == 0) g_flagF[b] = 1;
}

// ---------------- pipelined blocked backward solve L^T a = z -----------------
__global__ void bwd_solve_kernel() {
    extern __shared__ float sh[];
    float* Ls = sh;
    float* Lb = sh + 128*129;
    float* xs = Lb + 128*129;
    float* xc = xs + 128;
    int b = blockIdx.x, t = threadIdx.x;
    for (int idx = t; idx < NB*NB; idx += NB) {
        int r = idx >> 7, c = idx & 127;
        Ls[r*129 + c] = g_K[(b*NB+r)*NN + b*NB + c];
    }
    xs[t] = g_x[b*NB + t];
    __syncthreads();
    for (int c = NBLK-1; c > b; --c) {
        if (t == 0) { while (g_flagB[c] == 0) __nanosleep(20); }
        __syncthreads();
        __threadfence();
        for (int idx = t; idx < NB*NB; idx += NB) {
            int r = idx >> 7, cc = idx & 127;
            Lb[r*129 + cc] = g_K[(c*NB+r)*NN + b*NB + cc];
        }
        xc[t] = g_x[c*NB + t];
        __syncthreads();
        float s = 0.0f;
        #pragma unroll 8
        for (int r = 0; r < NB; ++r) s += Lb[r*129 + t] * xc[r];
        xs[t] -= s;
        __syncthreads();
    }
    for (int j = NB-1; j >= 0; --j) {
        if (t == j) xs[j] /= Ls[j*129 + j];
        __syncthreads();
        if (t < j) xs[t] -= Ls[j*129 + t] * xs[j];
        __syncthreads();
    }
    g_x[b*NB + t] = xs[t];
    __threadfence();
    __syncthreads();
    if (t == 0) g_flagB[b] = 1;
}

// ---------------- finalize: dot, logdet term, output -------------------------
__global__ void finalize_kernel(float* out, int out_size) {
    __shared__ double red[1024];
    int t = threadIdx.x;
    double s = 0.0;
    for (int i = t; i < NN; i += 1024) s += (double)g_yc[i] * (double)g_x[i];
    red[t] = s; __syncthreads();
    for (int o = 512; o > 0; o >>= 1) { if (t < o) red[t] += red[t+o]; __syncthreads(); }
    double dot = red[0];
    __syncthreads();
    double sl = 0.0;
    for (int i = t; i < NN; i += 1024) sl += log((double)g_K[i*NN + i]);
    red[t] = sl; __syncthreads();
    for (int o = 512; o > 0; o >>= 1) { if (t < o) red[t] += red[t+o]; __syncthreads(); }
    double sumlog = red[0];
    double A = 0.5 * (dot + sumlog);
    // B = log(clip(det(k_post), 1e-20)): det underflows fp32 -> clipped to TINY
    double B = -46.0517018598809136804;   // ln(1e-20)
    float result = (float)((A + B) / ((double)NN * (double)DD));
    for (int i = t; i < out_size; i += 1024) out[i] = result;
}

// ---------------- host launcher ----------------------------------------------
extern "C" void kernel_launch(void* const* d_in, const int* in_sizes, int n_in,
                              void* d_out, int out_size) {
    const float* X        = (const float*)d_in[0];
    const float* y        = (const float*)d_in[1];
    const float* X_bar    = (const float*)d_in[2];
    const float* lls      = (const float*)d_in[3];
    const float* lstd     = (const float*)d_in[4];
    const float* lnoise   = (const float*)d_in[5];
    const float* local_ls = (const float*)d_in[6];
    const float* gstd     = (const float*)d_in[7];
    const float* gnoise   = (const float*)d_in[8];
    float* out = (float*)d_out;

    size_t smLocal = (size_t)(128*129 + 256) * sizeof(float);          // 67 KB
    size_t smPotrf = (size_t)(128*129) * sizeof(float);                // 66 KB
    size_t smTrsm  = (size_t)(128*128 + 128*129) * sizeof(float);      // 129 KB
    size_t smSolve = (size_t)(2*128*129 + 256) * sizeof(float);        // 133 KB
    // Idempotent; persists from the (non-captured) correctness call.
    cudaFuncSetAttribute(local_chol_kernel, cudaFuncAttributeMaxDynamicSharedMemorySize, (int)smLocal);
    cudaFuncSetAttribute(potrf_kernel,      cudaFuncAttributeMaxDynamicSharedMemorySize, (int)smPotrf);
    cudaFuncSetAttribute(trsm_kernel,       cudaFuncAttributeMaxDynamicSharedMemorySize, (int)smTrsm);
    cudaFuncSetAttribute(fwd_solve_kernel,  cudaFuncAttributeMaxDynamicSharedMemorySize, (int)smSolve);
    cudaFuncSetAttribute(bwd_solve_kernel,  cudaFuncAttributeMaxDynamicSharedMemorySize, (int)smSolve);

    prep_kernel<<<1, 1024>>>(y);
    local_chol_kernel<<<DD, 128, smLocal>>>(X_bar, lls, lstd, lnoise, local_ls);
    compute_l_kernel<<<NN/128, 128>>>(X, X_bar, lls, lstd);
    {
        dim3 bk(32, 8);
        dim3 gk(NN/32, NN/8);
        buildK_kernel<<<gk, bk>>>(X, gstd, gnoise);
    }
    for (int k = 0; k < NBLK; ++k) {
        potrf_kernel<<<1, 128, smPotrf>>>(k);
        int rem = NN - (k+1)*NB;
        if (rem > 0) {
            trsm_kernel<<<NBLK-1-k, 128, smTrsm>>>(k);
            int nt = rem / 64;
            syrk_kernel<<<dim3(nt, nt), 256>>>(k);
        }
    }
    fwd_solve_kernel<<<NBLK, 128, smSolve>>>();
    bwd_solve_kernel<<<NBLK, 128, smSolve>>>();
    finalize_kernel<<<1, 1024>>>(out, out_size);
}

// round 2
// speedup vs baseline: 1.2745x; 1.2745x over previous
#include <cuda_runtime.h>
#include <math.h>

#define NN 3072
#define DD 3
#define MM 128
#define NB 128
#define NT (NN/NB)            // 24
#define NTILES (NT*(NT+1)/2)  // 300
#define JITTER_F 1e-8f

// ---------------- scratch (device globals; no allocations allowed) ----------
__device__ float g_K[NN*NN];            // kernel matrix / Cholesky factor (in-place)
__device__ float g_l[NN*DD];
__device__ float g_alpha[DD*MM];
__device__ float g_yc[NN];
__device__ float g_x[NN];
__device__ volatile int g_flagF[NT];
__device__ volatile int g_flagB[NT];
__device__ volatile int g_tflag[NT*NT];  // tile (i,j) final (L stored)

// ---------------- prep: mean-center y, reset flags --------------------------
__global__ void prep_kernel(const float* __restrict__ y) {
    __shared__ double red[1024];
    int t = threadIdx.x;
    double s = 0.0;
    for (int i = t; i < NN; i += 1024) s += (double)y[i];
    red[t] = s; __syncthreads();
    for (int o = 512; o > 0; o >>= 1) { if (t < o) red[t] += red[t+o]; __syncthreads(); }
    float mean = (float)(red[0] / (double)NN);
    for (int i = t; i < NN; i += 1024) {
        float v = y[i] - mean;
        g_yc[i] = v;
        g_x[i]  = v;
    }
    if (t < NT) { g_flagF[t] = 0; g_flagB[t] = 0; }
    if (t < NT*NT) g_tflag[t] = 0;
}

// ---------------- local GP: 128x128 chol + solve per dim (3 blocks) ---------
__global__ void local_chol_kernel(const float* __restrict__ X_bar,
                                  const float* __restrict__ lls,
                                  const float* __restrict__ lstd,
                                  const float* __restrict__ lnoise,
                                  const float* __restrict__ local_ls) {
    extern __shared__ float sh[];
    float* Ls = sh;                 // [128][129]
    float* xs = sh + 128*129;       // [128]
    float* xb = xs + 128;           // [128]
    int d = blockIdx.x;
    int t = threadIdx.x;
    float ls = lls[d], sd = lstd[d], no = lnoise[d];
    float inv2 = 0.5f / (ls*ls);
    float s2 = sd*sd;
    xb[t] = X_bar[t*DD + d];
    __syncthreads();
    float xt = xb[t];
    for (int j = 0; j < MM; ++j) {
        float diff = xt - xb[j];
        float dist = diff*diff;
        if (dist == 0.0f) dist = 1e-20f;
        float v = s2 * expf(-dist * inv2);
        if (j == t) v += no*no;
        Ls[t*129 + j] = v;
    }
    __syncthreads();
    for (int j = 0; j < MM; ++j) {
        if (t == 0) Ls[j*129 + j] = sqrtf(Ls[j*129 + j]);
        __syncthreads();
        float dj = Ls[j*129 + j];
        if (t > j) Ls[t*129 + j] /= dj;
        __syncthreads();
        if (t > j) {
            float ltj = Ls[t*129 + j];
            for (int c = j+1; c <= t; ++c) Ls[t*129 + c] -= ltj * Ls[c*129 + j];
        }
        __syncthreads();
    }
    xs[t] = logf(fabsf(local_ls[t*DD + d]));
    __syncthreads();
    for (int j = 0; j < MM; ++j) {
        if (t == j) xs[j] /= Ls[j*129 + j];
        __syncthreads();
        if (t > j) xs[t] -= Ls[t*129 + j] * xs[j];
        __syncthreads();
    }
    for (int j = MM-1; j >= 0; --j) {
        if (t == j) xs[j] /= Ls[j*129 + j];
        __syncthreads();
        if (t < j) xs[t] -= Ls[j*129 + t] * xs[j];
        __syncthreads();
    }
    g_alpha[d*MM + t] = xs[t];
}

// ---------------- l = exp(k_star @ alpha) ------------------------------------
__global__ void compute_l_kernel(const float* __restrict__ X,
                                 const float* __restrict__ X_bar,
                                 const float* __restrict__ lls,
                                 const float* __restrict__ lstd) {
    __shared__ float xb[DD][MM];
    __shared__ float al[DD][MM];
    int t = threadIdx.x;
    for (int d = 0; d < DD; ++d) {
        xb[d][t] = X_bar[t*DD + d];
        al[d][t] = g_alpha[d*MM + t];
    }
    __syncthreads();
    int i = blockIdx.x * 128 + t;
    for (int d = 0; d < DD; ++d) {
        float ls = lls[d], sd = lstd[d];
        float inv2 = 0.5f / (ls*ls);
        float s2 = sd*sd;
        float xi = X[i*DD + d];
        float acc = 0.0f;
        #pragma unroll 4
        for (int j = 0; j < MM; ++j) {
            float diff = xi - xb[d][j];
            acc += s2 * expf(-diff*diff*inv2) * al[d][j];
        }
        g_l[i*DD + d] = expf(acc);
    }
}

// ---------------- build global K matrix (lower 128-tiles only) ---------------
__global__ void buildK_kernel(const float* __restrict__ X,
                              const float* __restrict__ gstd,
                              const float* __restrict__ gnoise) {
    int jb = blockIdx.x*32, ib = blockIdx.y*8;
    if ((jb >> 7) > (ib >> 7)) return;  // strictly-upper tile: never read
    __shared__ float xj[32][DD], lj[32][DD], xi[8][DD], li[8][DD];
    int tx = threadIdx.x, ty = threadIdx.y;
    int lt = ty*32 + tx;
    if (lt < 32*DD) { int c = lt/DD, d = lt%DD; xj[c][d] = X[(jb+c)*DD+d]; lj[c][d] = g_l[(jb+c)*DD+d]; }
    else if (lt < 32*DD + 8*DD) { int q = lt - 32*DD; int r = q/DD, d = q%DD;
        xi[r][d] = X[(ib+r)*DD+d]; li[r][d] = g_l[(ib+r)*DD+d]; }
    __syncthreads();
    int j = jb + tx, i = ib + ty;
    float g2 = gstd[0]*gstd[0];
    float prod = 1.0f, sdist = 0.0f;
    #pragma unroll
    for (int d = 0; d < DD; ++d) {
        float a = li[ty][d], b = lj[tx][d];
        float inv = __fdividef(1.0f, a*a + b*b);
        prod *= 2.0f*a*b*inv;
        float diff = xi[ty][d] - xj[tx][d];
        sdist += diff*diff*inv;
    }
    float v = g2 * sqrtf(prod) * __expf(-sdist);
    if (i == j) v += gnoise[0]*gnoise[0] + JITTER_F;
    g_K[i*NN + j] = v;
}

// ---------------- single-kernel tile Cholesky (owner-computes + flags) -------
// Grid: 300 blocks, one per lower tile (i,j), column-major, diag first.
// Every wait targets a strictly lower block index -> deadlock-free with
// in-order dispatch; early blocks exit and free slots for later waves.
__global__ void __launch_bounds__(256, 2) chol_tile_kernel() {
    extern __shared__ float sh[];
    float* As = sh;                 // [128*17]   (update phase)
    float* Bs = sh + 128*17;        // [128*17]
    float* Ts = sh;                 // [128*129]  (final phase, overlays As/Bs)
    float* Ld = sh + 128*129;       // [128*33]   (panel phase: diag col-chunk)

    int b = blockIdx.x;
    int j = 0, rem = b;
    while (rem >= NT - j) { rem -= NT - j; ++j; }
    int i = j + rem;                 // rem==0 -> diag tile

    int t = threadIdx.x;
    int tx = t & 15, ty = t >> 4;
    const int rowbase = i*NB, colbase = j*NB;

    // load initial tile into 8x8 register accumulator (interleaved mapping)
    float acc[8][8];
    #pragma unroll
    for (int u = 0; u < 8; ++u)
        #pragma unroll
        for (int v = 0; v < 8; ++v)
            acc[u][v] = g_K[(size_t)(rowbase+ty+16*u)*NN + colbase+tx+16*v];

    // ---- accumulate updates: acc -= L(i,k) * L(j,k)^T -----------------------
    for (int k = 0; k < j; ++k) {
        if (t == 0) {
            while (g_tflag[i*NT+k] == 0) __nanosleep(40);
            while (g_tflag[j*NT+k] == 0) __nanosleep(40);
        }
        __syncthreads();
        __threadfence();
        const float* Ap = g_K + (size_t)rowbase*NN + k*NB;
        const float* Bp = g_K + (size_t)colbase*NN + k*NB;
        for (int p0 = 0; p0 < NB; p0 += 16) {
            #pragma unroll
            for (int q = 0; q < 8; ++q) {
                int idx = t + q*256;
                int r = idx >> 4, pp = idx & 15;
                As[r*17+pp] = Ap[(size_t)r*NN + p0+pp];
                Bs[r*17+pp] = Bp[(size_t)r*NN + p0+pp];
            }
            __syncthreads();
            #pragma unroll
            for (int p = 0; p < 16; ++p) {
                float ar[8], br[8];
                #pragma unroll
                for (int u = 0; u < 8; ++u) ar[u] = As[(ty+16*u)*17+p];
                #pragma unroll
                for (int v = 0; v < 8; ++v) br[v] = Bs[(tx+16*v)*17+p];
                #pragma unroll
                for (int u = 0; u < 8; ++u)
                    #pragma unroll
                    for (int v = 0; v < 8; ++v)
                        acc[u][v] -= ar[u]*br[v];
            }
            __syncthreads();
        }
    }

    // dump accumulator into smem tile Ts
    #pragma unroll
    for (int u = 0; u < 8; ++u)
        #pragma unroll
        for (int v = 0; v < 8; ++v)
            Ts[(ty+16*u)*129 + tx+16*v] = acc[u][v];
    __syncthreads();

    if (i == j) {
        // ---- blocked in-smem Cholesky of Ts (lower) -------------------------
        for (int p = 0; p < 4; ++p) {
            int base = 32*p;
            if (t < 32) {                 // warp 0: factor 32x32 diag block
                int lane = t;
                int r = base + lane;
                for (int c = 0; c < 32; ++c) {
                    int col = base + c;
                    if (lane == c) Ts[col*129+col] = sqrtf(Ts[col*129+col]);
                    __syncwarp();
                    float d = Ts[col*129+col];
                    float v = 0.0f;
                    if (lane > c) {
                        v = Ts[r*129+col] / d;
                        Ts[r*129+col] = v;
                    }
                    __syncwarp();
                    if (lane > c) {
                        for (int cc = c+1; cc <= lane; ++cc)
                            Ts[r*129+base+cc] -= v * Ts[(base+cc)*129+col];
                    }
                    __syncwarp();
                }
            }
            __syncthreads();
            int nrows = 128 - base - 32;
            if (nrows > 0) {
                if (t < nrows) {          // trsm rows below vs D^T
                    int r = base + 32 + t;
                    for (int c = 0; c < 32; ++c) {
                        int col = base + c;
                        float s = Ts[r*129+col];
                        for (int k2 = 0; k2 < c; ++k2)
                            s -= Ts[r*129+base+k2] * Ts[col*129+base+k2];
                        Ts[r*129+col] = s / Ts[col*129+col];
                    }
                }
                __syncthreads();
                int tot = nrows*nrows;    // syrk trailing (lower only)
                for (int idx = t; idx < tot; idx += 256) {
                    int r2 = idx / nrows, c2 = idx - r2*nrows;
                    if (c2 <= r2) {
                        int r = base+32+r2, c = base+32+c2;
                        float s = Ts[r*129+c];
                        #pragma unroll 8
                        for (int k2 = 0; k2 < 32; ++k2)
                            s -= Ts[r*129+base+k2] * Ts[c*129+base+k2];
                        Ts[r*129+c] = s;
                    }
                }
                __syncthreads();
            }
        }
    } else {
        // ---- panel: X = Ts * L(j,j)^-T via 32-col blocked trsm --------------
        if (t == 0) { while (g_tflag[j*NT+j] == 0) __nanosleep(40); }
        __syncthreads();
        __threadfence();
        const float* Djj = g_K + (size_t)colbase*NN + colbase;
        for (int c0 = 0; c0 < NB; c0 += 32) {
            #pragma unroll
            for (int q = 0; q < 16; ++q) {   // Ld[r][kk] = Djj[r][c0+kk]
                int idx = t + q*256;          // 4096 elements
                int r = idx >> 5, kk = idx & 31;
                Ld[r*33+kk] = Djj[(size_t)r*NN + c0 + kk];
            }
            __syncthreads();
            if (t < 128) {                    // short chains: 32-entry solve
                int r = t;
                for (int c = 0; c < 32; ++c) {
                    int col = c0 + c;
                    float s = Ts[r*129+col];
                    for (int k2 = 0; k2 < c; ++k2)
                        s -= Ts[r*129+c0+k2] * Ld[col*33+k2];
                    Ts[r*129+col] = s / Ld[col*33+c];
                }
            }
            __syncthreads();
            int rem2 = 128 - c0 - 32;
            if (rem2 > 0) {                   // parallel update of later cols
                int tot = 128*rem2;
                for (int idx = t; idx < tot; idx += 256) {
                    int r = idx / rem2;
                    int c2 = c0 + 32 + (idx - r*rem2);
                    float s = Ts[r*129+c2];
                    #pragma unroll 8
                    for (int k2 = 0; k2 < 32; ++k2)
                        s -= Ts[r*129+c0+k2] * Ld[c2*33+k2];
                    Ts[r*129+c2] = s;
                }
            }
            __syncthreads();
        }
    }

    // ---- store tile, fence, flag -------------------------------------------
    for (int idx = t; idx < NB*NB; idx += 256) {
        int r = idx >> 7, c = idx & 127;
        g_K[(size_t)(rowbase+r)*NN + colbase + c] = Ts[r*129+c];
    }
    __threadfence();
    __syncthreads();
    if (t == 0) g_tflag[i*NT+j] = 1;
}

// ---------------- pipelined blocked forward solve L z = yc -------------------
__global__ void fwd_solve_kernel() {
    extern __shared__ float sh[];
    float* Ls = sh;                  // [128][129] diag block
    float* Lb = sh + 128*129;        // [128][129] off-diag block
    float* xs = Lb + 128*129;        // [128]
    float* xc = xs + 128;            // [128]
    int b = blockIdx.x, t = threadIdx.x;
    for (int idx = t; idx < NB*NB; idx += NB) {
        int r = idx >> 7, c = idx & 127;
        Ls[r*129 + c] = g_K[(size_t)(b*NB+r)*NN + b*NB + c];
    }
    xs[t] = g_x[b*NB + t];
    __syncthreads();
    for (int c = 0; c < b; ++c) {
        if (t == 0) { while (g_flagF[c] == 0) __nanosleep(20); }
        __syncthreads();
        __threadfence();
        for (int idx = t; idx < NB*NB; idx += NB) {
            int r = idx >> 7, cc = idx & 127;
            Lb[r*129 + cc] = g_K[(size_t)(b*NB+r)*NN + c*NB + cc];
        }
        xc[t] = g_x[c*NB + t];
        __syncthreads();
        float s = 0.0f;
        float* lr = Lb + t*129;
        #pragma unroll 8
        for (int j = 0; j < NB; ++j) s += lr[j] * xc[j];
        xs[t] -= s;
        __syncthreads();
    }
    for (int j = 0; j < NB; ++j) {
        if (t == j) xs[j] /= Ls[j*129 + j];
        __syncthreads();
        if (t > j) xs[t] -= Ls[t*129 + j] * xs[j];
        __syncthreads();
    }
    g_x[b*NB + t] = xs[t];
    __threadfence();
    __syncthreads();
    if (t == 0) g_flagF[b] = 1;
}

// ---------------- pipelined blocked backward solve L^T a = z -----------------
__global__ void bwd_solve_kernel() {
    extern __shared__ float sh[];
    float* Ls = sh;
    float* Lb = sh + 128*129;
    float* xs = Lb + 128*129;
    float* xc = xs + 128;
    int b = blockIdx.x, t = threadIdx.x;
    for (int idx = t; idx < NB*NB; idx += NB) {
        int r = idx >> 7, c = idx & 127;
        Ls[r*129 + c] = g_K[(size_t)(b*NB+r)*NN + b*NB + c];
    }
    xs[t] = g_x[b*NB + t];
    __syncthreads();
    for (int c = NT-1; c > b; --c) {
        if (t == 0) { while (g_flagB[c] == 0) __nanosleep(20); }
        __syncthreads();
        __threadfence();
        for (int idx = t; idx < NB*NB; idx += NB) {
            int r = idx >> 7, cc = idx & 127;
            Lb[r*129 + cc] = g_K[(size_t)(c*NB+r)*NN + b*NB + cc];
        }
        xc[t] = g_x[c*NB + t];
        __syncthreads();
        float s = 0.0f;
        #pragma unroll 8
        for (int r = 0; r < NB; ++r) s += Lb[r*129 + t] * xc[r];
        xs[t] -= s;
        __syncthreads();
    }
    for (int j = NB-1; j >= 0; --j) {
        if (t == j) xs[j] /= Ls[j*129 + j];
        __syncthreads();
        if (t < j) xs[t] -= Ls[j*129 + t] * xs[j];
        __syncthreads();
    }
    g_x[b*NB + t] = xs[t];
    __threadfence();
    __syncthreads();
    if (t == 0) g_flagB[b] = 1;
}

// ---------------- finalize: dot, logdet term, output -------------------------
__global__ void finalize_kernel(float* out, int out_size) {
    __shared__ double red[1024];
    int t = threadIdx.x;
    double s = 0.0;
    for (int i = t; i < NN; i += 1024) s += (double)g_yc[i] * (double)g_x[i];
    red[t] = s; __syncthreads();
    for (int o = 512; o > 0; o >>= 1) { if (t < o) red[t] += red[t+o]; __syncthreads(); }
    double dot = red[0];
    __syncthreads();
    double sl = 0.0;
    for (int i = t; i < NN; i += 1024) sl += log((double)g_K[(size_t)i*NN + i]);
    red[t] = sl; __syncthreads();
    for (int o = 512; o > 0; o >>= 1) { if (t < o) red[t] += red[t+o]; __syncthreads(); }
    double sumlog = red[0];
    double A = 0.5 * (dot + sumlog);
    // B = log(clip(det(k_post), 1e-20)): det underflows fp32 -> clipped to TINY
    double B = -46.0517018598809136804;   // ln(1e-20)
    float result = (float)((A + B) / ((double)NN * (double)DD));
    for (int i = t; i < out_size; i += 1024) out[i] = result;
}

// ---------------- host launcher ----------------------------------------------
extern "C" void kernel_launch(void* const* d_in, const int* in_sizes, int n_in,
                              void* d_out, int out_size) {
    const float* X        = (const float*)d_in[0];
    const float* y        = (const float*)d_in[1];
    const float* X_bar    = (const float*)d_in[2];
    const float* lls      = (const float*)d_in[3];
    const float* lstd     = (const float*)d_in[4];
    const float* lnoise   = (const float*)d_in[5];
    const float* local_ls = (const float*)d_in[6];
    const float* gstd     = (const float*)d_in[7];
    const float* gnoise   = (const float*)d_in[8];
    float* out = (float*)d_out;

    size_t smLocal = (size_t)(128*129 + 256) * sizeof(float);          // 67 KB
    size_t smChol  = (size_t)(128*129 + 128*33) * sizeof(float);       // 83 KB
    size_t smSolve = (size_t)(2*128*129 + 256) * sizeof(float);        // 133 KB
    cudaFuncSetAttribute(local_chol_kernel, cudaFuncAttributeMaxDynamicSharedMemorySize, (int)smLocal);
    cudaFuncSetAttribute(chol_tile_kernel,  cudaFuncAttributeMaxDynamicSharedMemorySize, (int)smChol);
    cudaFuncSetAttribute(fwd_solve_kernel,  cudaFuncAttributeMaxDynamicSharedMemorySize, (int)smSolve);
    cudaFuncSetAttribute(bwd_solve_kernel,  cudaFuncAttributeMaxDynamicSharedMemorySize, (int)smSolve);

    prep_kernel<<<1, 1024>>>(y);
    local_chol_kernel<<<DD, 128, smLocal>>>(X_bar, lls, lstd, lnoise, local_ls);
    compute_l_kernel<<<NN/128, 128>>>(X, X_bar, lls, lstd);
    {
        dim3 bk(32, 8);
        dim3 gk(NN/32, NN/8);
        buildK_kernel<<<gk, bk>>>(X, gstd, gnoise);
    }
    chol_tile_kernel<<<NTILES, 256, smChol>>>();
    fwd_solve_kernel<<<NT, 128, smSolve>>>();
    bwd_solve_kernel<<<NT, 128, smSolve>>>();
    finalize_kernel<<<1, 1024>>>(out, out_size);
}

// round 3
// speedup vs baseline: 2.0386x; 1.5995x over previous
#include <cuda_runtime.h>
#include <math.h>

#define NN 3072
#define DD 3
#define MM 128
#define NB 128
#define NT (NN/NB)            // 24  (solve granularity)
#define NB2 64
#define NT2 (NN/NB2)          // 48  (factor granularity)
#define NTIL2 (NT2*(NT2+1)/2) // 1176
#define JITTER_F 1e-8f

// ---------------- scratch (device globals; no allocations allowed) ----------
__device__ float g_K[(size_t)NN*NN];    // kernel matrix / Cholesky factor (in-place)
__device__ float g_l[NN*DD];
__device__ float g_alpha[DD*MM];
__device__ float g_yc[NN];
__device__ float g_x[NN];
__device__ int g_flagF[NT];
__device__ int g_flagB[NT];
__device__ int g_tflag[NT2*NT2];

// ---------------- acquire/release helpers ------------------------------------
__device__ __forceinline__ int ldacq(const int* p) {
    int v;
    asm volatile("ld.acquire.gpu.b32 %0, [%1];" : "=r"(v) : "l"(p) : "memory");
    return v;
}
__device__ __forceinline__ void strel(int* p, int v) {
    asm volatile("st.release.gpu.b32 [%0], %1;" :: "l"(p), "r"(v) : "memory");
}

// ---------------- prep: mean-center y, reset flags ---------------------------
__global__ void prep_kernel(const float* __restrict__ y) {
    __shared__ double red[1024];
    int t = threadIdx.x;
    double s = 0.0;
    for (int i = t; i < NN; i += 1024) s += (double)y[i];
    red[t] = s; __syncthreads();
    for (int o = 512; o > 0; o >>= 1) { if (t < o) red[t] += red[t+o]; __syncthreads(); }
    float mean = (float)(red[0] / (double)NN);
    for (int i = t; i < NN; i += 1024) {
        float v = y[i] - mean;
        g_yc[i] = v;
        g_x[i]  = v;
    }
    if (t < NT) { g_flagF[t] = 0; g_flagB[t] = 0; }
    for (int i = t; i < NT2*NT2; i += 1024) g_tflag[i] = 0;
}

// ---------------- local GP: 128x128 chol + solve per dim (3 blocks) ----------
__global__ void local_chol_kernel(const float* __restrict__ X_bar,
                                  const float* __restrict__ lls,
                                  const float* __restrict__ lstd,
                                  const float* __restrict__ lnoise,
                                  const float* __restrict__ local_ls) {
    extern __shared__ float sh[];
    float* Ls = sh;                 // [128][129]
    float* xs = sh + 128*129;       // [128]
    float* xb = xs + 128;           // [128]
    int d = blockIdx.x;
    int t = threadIdx.x;
    float ls = lls[d], sd = lstd[d], no = lnoise[d];
    float inv2 = 0.5f / (ls*ls);
    float s2 = sd*sd;
    xb[t] = X_bar[t*DD + d];
    __syncthreads();
    float xt = xb[t];
    for (int j = 0; j < MM; ++j) {
        float diff = xt - xb[j];
        float dist = diff*diff;
        if (dist == 0.0f) dist = 1e-20f;
        float v = s2 * expf(-dist * inv2);
        if (j == t) v += no*no;
        Ls[t*129 + j] = v;
    }
    __syncthreads();
    for (int j = 0; j < MM; ++j) {
        if (t == 0) Ls[j*129 + j] = sqrtf(Ls[j*129 + j]);
        __syncthreads();
        float dj = Ls[j*129 + j];
        if (t > j) Ls[t*129 + j] /= dj;
        __syncthreads();
        if (t > j) {
            float ltj = Ls[t*129 + j];
            for (int c = j+1; c <= t; ++c) Ls[t*129 + c] -= ltj * Ls[c*129 + j];
        }
        __syncthreads();
    }
    xs[t] = logf(fabsf(local_ls[t*DD + d]));
    __syncthreads();
    for (int j = 0; j < MM; ++j) {
        if (t == j) xs[j] /= Ls[j*129 + j];
        __syncthreads();
        if (t > j) xs[t] -= Ls[t*129 + j] * xs[j];
        __syncthreads();
    }
    for (int j = MM-1; j >= 0; --j) {
        if (t == j) xs[j] /= Ls[j*129 + j];
        __syncthreads();
        if (t < j) xs[t] -= Ls[j*129 + t] * xs[j];
        __syncthreads();
    }
    g_alpha[d*MM + t] = xs[t];
}

// ---------------- l = exp(k_star @ alpha) ------------------------------------
__global__ void compute_l_kernel(const float* __restrict__ X,
                                 const float* __restrict__ X_bar,
                                 const float* __restrict__ lls,
                                 const float* __restrict__ lstd) {
    __shared__ float xb[DD][MM];
    __shared__ float al[DD][MM];
    int t = threadIdx.x;
    for (int d = 0; d < DD; ++d) {
        xb[d][t] = X_bar[t*DD + d];
        al[d][t] = g_alpha[d*MM + t];
    }
    __syncthreads();
    int i = blockIdx.x * 128 + t;
    for (int d = 0; d < DD; ++d) {
        float ls = lls[d], sd = lstd[d];
        float inv2 = 0.5f / (ls*ls);
        float s2 = sd*sd;
        float xi = X[i*DD + d];
        float acc = 0.0f;
        #pragma unroll 4
        for (int j = 0; j < MM; ++j) {
            float diff = xi - xb[d][j];
            acc += s2 * expf(-diff*diff*inv2) * al[d][j];
        }
        g_l[i*DD + d] = expf(acc);
    }
}

// ---------------- persistent NB=64 tile Cholesky (builds K in-kernel) --------
// 1176 tiles column-major diag-first; deps point to strictly lower tile index;
// each block processes ascending indices -> deadlock-free for any residency.
__global__ void __launch_bounds__(256, 4) chol64_kernel(
        const float* __restrict__ X,
        const float* __restrict__ gstd,
        const float* __restrict__ gnoise) {
    extern __shared__ float sh[];
    float* Ts = sh;            // [64][65] = 4160 floats
    float* U  = sh + 4160;     // 2176 floats: build staging / As+Bs / Ds
    float* As = U;             // [64][17]
    float* Bs = U + 1088;      // [64][17]
    float* Ds = U;             // [<=64][33] (trsm diag staging)

    int t = threadIdx.x;
    int tx = t & 15, ty = t >> 4;
    float g2 = gstd[0]*gstd[0];
    float ndiag = gnoise[0]*gnoise[0] + JITTER_F;

    for (int w = blockIdx.x; w < NTIL2; w += gridDim.x) {
        int j = 0, rem = w;
        while (rem >= NT2 - j) { rem -= NT2 - j; ++j; }
        int i = j + rem;
        const int rowbase = i*NB2, colbase = j*NB2;
        const size_t rN = (size_t)rowbase * NN;
        const size_t cN = (size_t)colbase * NN;

        // ---- build phase: compute this K tile directly ----------------------
        __syncthreads();
        if (t < 192) {
            U[t]       = X  [rowbase*DD + t];
            U[192+t]   = g_l[rowbase*DD + t];
            U[384+t]   = X  [colbase*DD + t];
            U[576+t]   = g_l[colbase*DD + t];
        }
        __syncthreads();
        float acc[4][4];
        #pragma unroll
        for (int u = 0; u < 4; ++u) {
            int r = ty + 16*u;
            #pragma unroll
            for (int v = 0; v < 4; ++v) {
                int c = tx + 16*v;
                float prod = 1.0f, sdist = 0.0f;
                #pragma unroll
                for (int d = 0; d < DD; ++d) {
                    float a = U[192 + r*DD + d], bl = U[576 + c*DD + d];
                    float inv = __fdividef(1.0f, a*a + bl*bl);
                    prod *= 2.0f*a*bl*inv;
                    float df = U[r*DD + d] - U[384 + c*DD + d];
                    sdist += df*df*inv;
                }
                float val = g2 * sqrtf(prod) * __expf(-sdist);
                if (i == j && r == c) val += ndiag;
                acc[u][v] = val;
            }
        }
        __syncthreads();

        // ---- update phase: acc -= L(i,k) * L(j,k)^T -------------------------
        for (int k = 0; k < j; ++k) {
            if (t == 0) {
                while (ldacq(&g_tflag[i*NT2 + k]) == 0) __nanosleep(40);
                if (i != j)
                    while (ldacq(&g_tflag[j*NT2 + k]) == 0) __nanosleep(40);
            }
            __syncthreads();
            const float* Ap = g_K + rN + k*NB2;
            const float* Bp = g_K + cN + k*NB2;
            #pragma unroll 1
            for (int p0 = 0; p0 < NB2; p0 += 16) {
                #pragma unroll
                for (int q = 0; q < 4; ++q) {
                    int idx = t + q*256;
                    int r = idx >> 4, pp = idx & 15;
                    As[r*17 + pp] = Ap[(size_t)r*NN + p0 + pp];
                    Bs[r*17 + pp] = Bp[(size_t)r*NN + p0 + pp];
                }
                __syncthreads();
                #pragma unroll
                for (int p = 0; p < 16; ++p) {
                    float ar[4], br[4];
                    #pragma unroll
                    for (int u = 0; u < 4; ++u) ar[u] = As[(ty+16*u)*17 + p];
                    #pragma unroll
                    for (int v = 0; v < 4; ++v) br[v] = Bs[(tx+16*v)*17 + p];
                    #pragma unroll
                    for (int u = 0; u < 4; ++u)
                        #pragma unroll
                        for (int v = 0; v < 4; ++v)
                            acc[u][v] -= ar[u]*br[v];
                }
                __syncthreads();
            }
        }

        // dump accumulator into Ts
        #pragma unroll
        for (int u = 0; u < 4; ++u)
            #pragma unroll
            for (int v = 0; v < 4; ++v)
                Ts[(ty+16*u)*65 + tx+16*v] = acc[u][v];
        __syncthreads();

        if (i == j) {
            // ---- diag factor: 2 rounds of 32 --------------------------------
            // round 0: warp0 factors D00
            if (t < 32) {
                int l = t;
                for (int c = 0; c < 32; ++c) {
                    if (l == c) Ts[c*65+c] = sqrtf(Ts[c*65+c]);
                    __syncwarp();
                    float dd = Ts[c*65+c];
                    float v = 0.0f;
                    if (l > c) { v = __fdividef(Ts[l*65+c], dd); Ts[l*65+c] = v; }
                    __syncwarp();
                    if (l > c)
                        for (int cc = c+1; cc <= l; ++cc)
                            Ts[l*65+cc] -= v * Ts[cc*65+c];
                    __syncwarp();
                }
            }
            __syncthreads();
            // trsm rows 32..63 vs D00^T (warp1, one row each)
            if (t >= 32 && t < 64) {
                int r = t;
                for (int c = 0; c < 32; ++c) {
                    float s = Ts[r*65+c];
                    for (int k2 = 0; k2 < c; ++k2) s -= Ts[r*65+k2] * Ts[c*65+k2];
                    Ts[r*65+c] = __fdividef(s, Ts[c*65+c]);
                }
            }
            __syncthreads();
            // syrk trailing 32x32 (lower)
            for (int idx = t; idx < 32*32; idx += 256) {
                int r2 = idx >> 5, c2 = idx & 31;
                if (c2 <= r2) {
                    float s = Ts[(32+r2)*65 + 32+c2];
                    #pragma unroll 8
                    for (int k2 = 0; k2 < 32; ++k2)
                        s -= Ts[(32+r2)*65 + k2] * Ts[(32+c2)*65 + k2];
                    Ts[(32+r2)*65 + 32+c2] = s;
                }
            }
            __syncthreads();
            // round 1: warp0 factors D11
            if (t < 32) {
                int l = t;
                for (int c = 0; c < 32; ++c) {
                    int C = 32+c, R = 32+l;
                    if (l == c) Ts[C*65+C] = sqrtf(Ts[C*65+C]);
                    __syncwarp();
                    float dd = Ts[C*65+C];
                    float v = 0.0f;
                    if (l > c) { v = __fdividef(Ts[R*65+C], dd); Ts[R*65+C] = v; }
                    __syncwarp();
                    if (l > c)
                        for (int cc = c+1; cc <= l; ++cc)
                            Ts[R*65+32+cc] -= v * Ts[(32+cc)*65+C];
                    __syncwarp();
                }
            }
            __syncthreads();
        } else {
            // ---- panel trsm: Ts = Ts * L(j,j)^-T, 32-col chunks -------------
            if (t == 0) { while (ldacq(&g_tflag[j*NT2 + j]) == 0) __nanosleep(40); }
            __syncthreads();
            const float* Dg = g_K + cN + colbase;   // diag tile (final)
            for (int c0 = 0; c0 < NB2; c0 += 32) {
                int nrows = NB2 - c0;
                for (int idx = t; idx < nrows*32; idx += 256) {
                    int rr = idx >> 5, kk = idx & 31;
                    Ds[rr*33 + kk] = Dg[(size_t)(c0+rr)*NN + c0 + kk];
                }
                __syncthreads();
                if (t < 64) {
                    int r = t;
                    for (int c = 0; c < 32; ++c) {
                        float s = Ts[r*65 + c0 + c];
                        for (int k2 = 0; k2 < c; ++k2)
                            s -= Ts[r*65 + c0 + k2] * Ds[c*33 + k2];
                        Ts[r*65 + c0 + c] = __fdividef(s, Ds[c*33 + c]);
                    }
                }
                __syncthreads();
                if (c0 == 0) {
                    // update cols 32..63 with solved chunk
                    for (int idx = t; idx < 64*32; idx += 256) {
                        int r = idx >> 5, c2 = 32 + (idx & 31);
                        float s = Ts[r*65 + c2];
                        #pragma unroll 8
                        for (int k2 = 0; k2 < 32; ++k2)
                            s -= Ts[r*65 + k2] * Ds[c2*33 + k2];
                        Ts[r*65 + c2] = s;
                    }
                    __syncthreads();
                }
            }
        }

        // ---- store tile, release flag ---------------------------------------
        for (int idx = t; idx < NB2*NB2; idx += 256) {
            int r = idx >> 6, c = idx & 63;
            g_K[rN + (size_t)r*NN + colbase + c] = Ts[r*65 + c];
        }
        __syncthreads();
        if (t == 0) strel(&g_tflag[i*NT2 + j], 1);
    }
}

// ---------------- merged pipelined solve: fwd + bwd + finalize ---------------
__global__ void solve_kernel(float* out, int out_size) {
    extern __shared__ float sh[];
    float* Ls = sh;                 // [128][129] diag block (kept for both phases)
    float* Lb = sh + 16512;         // [128][129] off-diag staging
    float* xs = sh + 33024;         // [128]
    float* xc = xs + 128;           // [128]
    double* red = (double*)(xc + 128);  // [128]
    int b = blockIdx.x, t = threadIdx.x;

    for (int idx = t; idx < 128*128; idx += 128) {
        int r = idx >> 7, c = idx & 127;
        Ls[r*129 + c] = g_K[(size_t)(b*128+r)*NN + b*128 + c];
    }
    float v = g_x[b*128 + t];
    __syncthreads();

    // ---- forward: L z = yc ----------------------------------------------------
    for (int c = 0; c < b; ++c) {
        for (int idx = t; idx < 128*128; idx += 128) {      // static tile: prefetch before wait
            int r = idx >> 7, cc = idx & 127;
            Lb[r*129 + cc] = g_K[(size_t)(b*128+r)*NN + c*128 + cc];
        }
        if (t == 0) { while (ldacq(&g_flagF[c]) == 0) __nanosleep(20); }
        __syncthreads();
        xc[t] = g_x[c*128 + t];
        __syncthreads();
        float s0=0,s1=0,s2=0,s3=0;
        const float* lr = Lb + t*129;
        #pragma unroll 8
        for (int jj = 0; jj < 128; jj += 4) {
            s0 += lr[jj  ]*xc[jj  ]; s1 += lr[jj+1]*xc[jj+1];
            s2 += lr[jj+2]*xc[jj+2]; s3 += lr[jj+3]*xc[jj+3];
        }
        v -= (s0+s1)+(s2+s3);
        __syncthreads();
    }
    // diag solve blocked-32 (warp-shfl inner)
    for (int p = 0; p < 4; ++p) {
        int base = 32*p;
        if ((t >> 5) == p) {
            int l = t - base;
            float x = 0.0f;
            for (int c = 0; c < 32; ++c) {
                float tv = 0.0f;
                if (l == c) { x = __fdividef(v, Ls[(base+c)*129 + base+c]); tv = x; }
                tv = __shfl_sync(0xffffffffu, tv, c);
                if (l > c) v -= Ls[t*129 + base+c] * tv;
            }
            xs[t] = x;
        }
        __syncthreads();
        if (t >= base + 32) {
            float s = 0.0f;
            #pragma unroll
            for (int k = 0; k < 32; ++k) s += Ls[t*129 + base+k] * xs[base+k];
            v -= s;
        }
    }
    __syncthreads();
    g_x[b*128 + t] = xs[t];
    __syncthreads();
    if (t == 0) strel(&g_flagF[b], 1);

    // ---- backward: L^T a = z --------------------------------------------------
    v = xs[t];
    for (int c = NT-1; c > b; --c) {
        for (int idx = t; idx < 128*128; idx += 128) {
            int r = idx >> 7, cc = idx & 127;
            Lb[r*129 + cc] = g_K[(size_t)(c*128+r)*NN + b*128 + cc];
        }
        if (t == 0) { while (ldacq(&g_flagB[c]) == 0) __nanosleep(20); }
        __syncthreads();
        xc[t] = g_x[c*128 + t];
        __syncthreads();
        float s0=0,s1=0,s2=0,s3=0;
        #pragma unroll 8
        for (int r = 0; r < 128; r += 4) {
            s0 += Lb[(r  )*129 + t]*xc[r  ]; s1 += Lb[(r+1)*129 + t]*xc[r+1];
            s2 += Lb[(r+2)*129 + t]*xc[r+2]; s3 += Lb[(r+3)*129 + t]*xc[r+3];
        }
        v -= (s0+s1)+(s2+s3);
        __syncthreads();
    }
    for (int p = 3; p >= 0; --p) {
        int base = 32*p;
        if ((t >> 5) == p) {
            int l = t - base;
            float x = 0.0f;
            for (int c = 31; c >= 0; --c) {
                float tv = 0.0f;
                if (l == c) { x = __fdividef(v, Ls[(base+c)*129 + base+c]); tv = x; }
                tv = __shfl_sync(0xffffffffu, tv, c);
                if (l < c) v -= Ls[(base+c)*129 + t] * tv;
            }
            xs[t] = x;
        }
        __syncthreads();
        if (t < base) {
            float s = 0.0f;
            #pragma unroll
            for (int k = 0; k < 32; ++k) s += Ls[(base+k)*129 + t] * xs[base+k];
            v -= s;
        }
    }
    __syncthreads();
    g_x[b*128 + t] = xs[t];
    __syncthreads();
    if (t == 0) strel(&g_flagB[b], 1);

    // ---- finalize (block 0 finishes last in bwd => all data final) -----------
    if (b == 0) {
        double s = 0.0;
        for (int ii = t; ii < NN; ii += 128) s += (double)g_yc[ii] * (double)g_x[ii];
        red[t] = s; __syncthreads();
        for (int o = 64; o > 0; o >>= 1) { if (t < o) red[t] += red[t+o]; __syncthreads(); }
        double dot = red[0]; __syncthreads();
        double sl = 0.0;
        for (int ii = t; ii < NN; ii += 128) sl += log((double)g_K[(size_t)ii*NN + ii]);
        red[t] = sl; __syncthreads();
        for (int o = 64; o > 0; o >>= 1) { if (t < o) red[t] += red[t+o]; __syncthreads(); }
        double A = 0.5 * (dot + red[0]);
        // B = log(clip(det(k_post), 1e-20)): fp32 det underflows -> TINY
        double B = -46.0517018598809136804;
        float result = (float)((A + B) / ((double)NN * (double)DD));
        for (int ii = t; ii < out_size; ii += 128) out[ii] = result;
    }
}

// ---------------- host launcher ----------------------------------------------
extern "C" void kernel_launch(void* const* d_in, const int* in_sizes, int n_in,
                              void* d_out, int out_size) {
    const float* X        = (const float*)d_in[0];
    const float* y        = (const float*)d_in[1];
    const float* X_bar    = (const float*)d_in[2];
    const float* lls      = (const float*)d_in[3];
    const float* lstd     = (const float*)d_in[4];
    const float* lnoise   = (const float*)d_in[5];
    const float* local_ls = (const float*)d_in[6];
    const float* gstd     = (const float*)d_in[7];
    const float* gnoise   = (const float*)d_in[8];
    float* out = (float*)d_out;

    size_t smLocal = (size_t)(128*129 + 256) * sizeof(float);            // 67 KB
    size_t smChol  = (size_t)(64*65 + 2176) * sizeof(float);             // 25.3 KB
    size_t smSolve = (size_t)(2*128*129 + 256) * sizeof(float) + 128*sizeof(double); // 134 KB
    cudaFuncSetAttribute(local_chol_kernel, cudaFuncAttributeMaxDynamicSharedMemorySize, (int)smLocal);
    cudaFuncSetAttribute(chol64_kernel,     cudaFuncAttributeMaxDynamicSharedMemorySize, (int)smChol);
    cudaFuncSetAttribute(solve_kernel,      cudaFuncAttributeMaxDynamicSharedMemorySize, (int)smSolve);

    prep_kernel<<<1, 1024>>>(y);
    local_chol_kernel<<<DD, 128, smLocal>>>(X_bar, lls, lstd, lnoise, local_ls);
    compute_l_kernel<<<NN/128, 128>>>(X, X_bar, lls, lstd);
    chol64_kernel<<<592, 256, smChol>>>(X, gstd, gnoise);
    solve_kernel<<<NT, 128, smSolve>>>(out, out_size);
}